// round 8
// baseline (speedup 1.0000x reference)
#include <cuda_runtime.h>
#include <cuda_fp16.h>
#include <math.h>
#include <stdint.h>

#define NU 100000
#define NI 100000
#define NE 300000
#define NROWS (NU + NI)
#define NTILES 1563
#define G3 384
#define MDIM 512

__device__ int    d_lastU[NU];
__device__ int    d_lastV[NI];
__device__ __half d_hWi[G3 * MDIM];
__device__ __half d_hWh[G3 * 128];
__device__ float  d_G1[(size_t)NROWS * G3];

// ---------------------------------------------------------------------------
__global__ void k_init_last() {
    int i = blockIdx.x * blockDim.x + threadIdx.x;
    if (i < NU) d_lastU[i] = -1;
    if (i < NI) d_lastV[i] = -1;
}

__global__ void k_scan_edges(const int* __restrict__ src, const int* __restrict__ dst) {
    int i = blockIdx.x * blockDim.x + threadIdx.x;
    if (i < NE) {
        atomicMax(&d_lastU[src[i]], i);
        atomicMax(&d_lastV[dst[i]], i);
    }
}

__global__ void k_cvt_w(const float* __restrict__ Wi, const float* __restrict__ Wh) {
    int i = blockIdx.x * blockDim.x + threadIdx.x;
    if (i < G3 * MDIM) d_hWi[i] = __float2half(Wi[i]);
    if (i < G3 * 128)  d_hWh[i] = __float2half(Wh[i]);
}

// ---------------------------------------------------------------------------
__device__ __forceinline__ uint32_t smem_u32(const void* p) {
    uint32_t a;
    asm("{ .reg .u64 t; cvta.to.shared.u64 t, %1; cvt.u32.u64 %0, t; }" : "=r"(a) : "l"(p));
    return a;
}
__device__ __forceinline__ void cp16(uint32_t dst, const void* src) {
    asm volatile("cp.async.cg.shared.global [%0], [%1], 16;"
                 :: "r"(dst), "l"(src) : "memory");
}
#define CP_COMMIT() asm volatile("cp.async.commit_group;" ::: "memory")
#define CP_WAIT2()  asm volatile("cp.async.wait_group 2;" ::: "memory")

__device__ __forceinline__ void ldsm4(uint32_t& r0, uint32_t& r1, uint32_t& r2,
                                      uint32_t& r3, uint32_t a) {
    asm volatile("ldmatrix.sync.aligned.m8n8.x4.shared.b16 {%0,%1,%2,%3}, [%4];"
                 : "=r"(r0), "=r"(r1), "=r"(r2), "=r"(r3) : "r"(a));
}
__device__ __forceinline__ void mma_f16(float c[4], uint32_t a0, uint32_t a1,
                                        uint32_t a2, uint32_t a3,
                                        uint32_t b0, uint32_t b1) {
    asm volatile(
        "mma.sync.aligned.m16n8k16.row.col.f32.f16.f16.f32 "
        "{%0,%1,%2,%3}, {%4,%5,%6,%7}, {%8,%9}, {%0,%1,%2,%3};"
        : "+f"(c[0]), "+f"(c[1]), "+f"(c[2]), "+f"(c[3])
        : "r"(a0), "r"(a1), "r"(a2), "r"(a3), "r"(b0), "r"(b1));
}
__device__ __forceinline__ uint32_t h2u(__half2 h) { return *(uint32_t*)&h; }
__device__ __forceinline__ float sigf(float x) { return 1.f / (1.f + expf(-x)); }

// swizzled byte offset within one [128 rows x 32 halves] 8KB chunk
__device__ __forceinline__ uint32_t sw_off(int m, int u) {
    return (uint32_t)((m << 6) + (((u ^ ((m >> 1) & 3)) & 3) << 4));
}

// ===========================================================================
// Kernel 1: fused gather/build-X (smem-resident) + GEMM1 -> d_G1
// 512 threads, 16 warps (4M x 4N), CTA tile 128 rows x 128 cols x 3 n-tiles.
// smem: X 128KB (16 chunks of 8KB) | B stages 32KB | meta 1.5KB
#define K1_XB    0
#define K1_BB    131072
#define K1_META  163840
#define K1_SMEM  (K1_META + 1536)

__global__ __launch_bounds__(512, 1)
void k_gemm1f(const float* __restrict__ si, const float* __restrict__ sj,
              const float* __restrict__ t,  const float* __restrict__ efeat,
              const int* __restrict__ src,  const int* __restrict__ dst,
              const float* __restrict__ freq) {
    extern __shared__ char smraw[];
    const uint32_t sbX = smem_u32(smraw) + K1_XB;
    const uint32_t sbB = smem_u32(smraw) + K1_BB;
    int*   s_le = (int*)(smraw + K1_META);
    int*   s_ot = s_le + 128;
    float* s_tv = (float*)(s_ot + 128);

    const int tid  = threadIdx.x;
    const int lane = tid & 31;
    const int w    = tid >> 5;
    const int wm   = w & 3;
    const int wn   = w >> 2;
    const int g    = lane >> 2;
    const int tg   = lane & 3;
    const int m0   = blockIdx.x * 128;

    if (tid < 128) {
        int gr = m0 + tid;
        int le = -1, ot = 0; float tv = 0.f;
        if (gr < NU) {
            le = d_lastU[gr];
            if (le >= 0) { ot = dst[le]; tv = t[le]; }
        } else if (gr < NROWS) {
            le = d_lastV[gr - NU];
            if (le >= 0) { ot = src[le]; tv = t[le]; }
        }
        s_le[tid] = le; s_ot[tid] = ot; s_tv[tid] = tv;
    }
    __syncthreads();

    // ---- build X in smem: 8192 16B-units; thread covers (row-slice, unit)
    {
        const int bm = tid >> 6;        // 0..7
        const int u  = tid & 63;        // unit within row
        const int sec  = u >> 4;        // 0..3
        const int colu = (u & 15) * 8;  // float col within section
#pragma unroll 1
        for (int i = 0; i < 16; ++i) {
            const int m  = bm + 8 * i;
            const int gr = m0 + m;
            const int le = s_le[m];
            float v[8];
            if (le < 0) {
#pragma unroll
                for (int k = 0; k < 8; ++k) v[k] = 0.f;
            } else if (sec == 2) {
                const float tv = s_tv[m];
#pragma unroll
                for (int k = 0; k < 8; ++k) v[k] = __cosf(tv * __ldg(freq + colu + k));
            } else {
                const float* p;
                if (sec == 0) {
                    const int ot = s_ot[m];
                    p = ((gr < NU) ? sj : si) + (size_t)ot * 128 + colu;
                } else if (sec == 1) {
                    p = ((gr < NU) ? si + (size_t)gr * 128
                                   : sj + (size_t)(gr - NU) * 128) + colu;
                } else {
                    p = efeat + (size_t)le * 128 + colu;
                }
                float4 a = __ldg((const float4*)p);
                float4 b = __ldg((const float4*)(p + 4));
                v[0]=a.x; v[1]=a.y; v[2]=a.z; v[3]=a.w;
                v[4]=b.x; v[5]=b.y; v[6]=b.z; v[7]=b.w;
            }
            uint32_t h0 = h2u(__floats2half2_rn(v[0], v[1]));
            uint32_t h1 = h2u(__floats2half2_rn(v[2], v[3]));
            uint32_t h2_ = h2u(__floats2half2_rn(v[4], v[5]));
            uint32_t h3 = h2u(__floats2half2_rn(v[6], v[7]));
            uint32_t addr = sbX + (u >> 2) * 8192 + sw_off(m, u & 3);
            asm volatile("st.shared.v4.b32 [%0], {%1,%2,%3,%4};"
                         :: "r"(addr), "r"(h0), "r"(h1), "r"(h2_), "r"(h3) : "memory");
        }
    }
    __syncthreads();

    // ---- ldmatrix per-lane offsets
    uint32_t offA[2][2], offB[2][2];
    {
        const int mr = lane & 15;
        const int uu = lane >> 4;
#pragma unroll
        for (int im = 0; im < 2; ++im)
#pragma unroll
            for (int kk = 0; kk < 2; ++kk)
                offA[im][kk] = sw_off(wm * 32 + im * 16 + mr, kk * 2 + uu);
#pragma unroll
        for (int j = 0; j < 2; ++j)
#pragma unroll
            for (int kk = 0; kk < 2; ++kk)
                offB[j][kk] = sw_off(wn * 32 + j * 16 + mr, kk * 2 + uu);
    }

    // B cp.async slots
    const int brow = tid >> 2;
    const int bu   = tid & 3;
    const uint32_t dB = sw_off(brow, bu);

#pragma unroll 1
    for (int nt = 0; nt < 3; ++nt) {
        const __half* bP = d_hWi + (size_t)(nt * 128 + brow) * MDIM + bu * 8;

#pragma unroll
        for (int s = 0; s < 3; ++s) {
            cp16(sbB + s * 8192 + dB, bP + s * 32);
            CP_COMMIT();
        }

        float acc[2][4][4];
#pragma unroll
        for (int i = 0; i < 2; ++i)
#pragma unroll
            for (int j = 0; j < 4; ++j)
#pragma unroll
                for (int c = 0; c < 4; ++c) acc[i][j][c] = 0.f;

#pragma unroll 1
        for (int c = 0; c < 16; ++c) {
            CP_WAIT2();
            __syncthreads();
            if (c + 3 < 16)
                cp16(sbB + ((c + 3) & 3) * 8192 + dB, bP + (c + 3) * 32);
            CP_COMMIT();

            const uint32_t xc  = sbX + c * 8192;
            const uint32_t stg = sbB + (c & 3) * 8192;
#pragma unroll
            for (int kk = 0; kk < 2; ++kk) {
                uint32_t a[2][4], b[2][4];
#pragma unroll
                for (int im = 0; im < 2; ++im)
                    ldsm4(a[im][0], a[im][1], a[im][2], a[im][3], xc + offA[im][kk]);
#pragma unroll
                for (int j = 0; j < 2; ++j)
                    ldsm4(b[j][0], b[j][1], b[j][2], b[j][3], stg + offB[j][kk]);
#pragma unroll
                for (int im = 0; im < 2; ++im) {
                    mma_f16(acc[im][0], a[im][0], a[im][1], a[im][2], a[im][3],
                            b[0][0], b[0][2]);
                    mma_f16(acc[im][1], a[im][0], a[im][1], a[im][2], a[im][3],
                            b[0][1], b[0][3]);
                    mma_f16(acc[im][2], a[im][0], a[im][1], a[im][2], a[im][3],
                            b[1][0], b[1][2]);
                    mma_f16(acc[im][3], a[im][0], a[im][1], a[im][2], a[im][3],
                            b[1][1], b[1][3]);
                }
            }
        }

        // write G1 n-tile
#pragma unroll
        for (int im = 0; im < 2; ++im) {
#pragma unroll
            for (int in_ = 0; in_ < 4; ++in_) {
                const int row = m0 + wm * 32 + im * 16 + g;
                const int col = nt * 128 + wn * 32 + in_ * 8 + tg * 2;
                if (row < NROWS)
                    *(float2*)(d_G1 + (size_t)row * G3 + col) =
                        make_float2(acc[im][in_][0], acc[im][in_][1]);
                if (row + 8 < NROWS)
                    *(float2*)(d_G1 + (size_t)(row + 8) * G3 + col) =
                        make_float2(acc[im][in_][2], acc[im][in_][3]);
            }
        }
        __syncthreads();   // stages safe to reuse in next n-tile
    }
}

// ===========================================================================
// Kernel 2: fused GEMM2 (H @ Wh^T) + GRU combine -> out
// 512 threads, CTA tile 128 rows; 3 n-tiles pipelined over 12 B-chunks.
// smem: h 32KB | B stages 32KB | Gsum 2x(128x132) fp32  (even stride: float2 ok)
#define K2_HB   0
#define K2_BB   32768
#define K2_GS   65536
#define GSS     132
#define K2_SMEM (K2_GS + 2 * 128 * GSS * 4)   // 200704

__global__ __launch_bounds__(512, 1)
void k_gemm2f(const float* __restrict__ si, const float* __restrict__ sj,
              const float* __restrict__ bi, const float* __restrict__ bh,
              float* __restrict__ out) {
    extern __shared__ char smraw[];
    const uint32_t sbH = smem_u32(smraw) + K2_HB;
    const uint32_t sbB = smem_u32(smraw) + K2_BB;
    float* Gs0 = (float*)(smraw + K2_GS);
    float* Gs1 = Gs0 + 128 * GSS;

    const int tid  = threadIdx.x;
    const int lane = tid & 31;
    const int w    = tid >> 5;
    const int wm   = w & 3;
    const int wn   = w >> 2;
    const int g    = lane >> 2;
    const int tg   = lane & 3;
    const int m0   = blockIdx.x * 128;

    // ---- build h tile (fp16, swizzled): 2048 units, 4 per thread
#pragma unroll
    for (int i = 0; i < 4; ++i) {
        const int idx = tid + 512 * i;
        const int m = idx >> 4;
        const int u = idx & 15;
        const int gr = m0 + m;
        float v[8];
        if (gr < NROWS) {
            const float* p = ((gr < NU) ? si + (size_t)gr * 128
                                        : sj + (size_t)(gr - NU) * 128) + u * 8;
            float4 a = __ldg((const float4*)p);
            float4 b = __ldg((const float4*)(p + 4));
            v[0]=a.x; v[1]=a.y; v[2]=a.z; v[3]=a.w;
            v[4]=b.x; v[5]=b.y; v[6]=b.z; v[7]=b.w;
        } else {
#pragma unroll
            for (int k = 0; k < 8; ++k) v[k] = 0.f;
        }
        uint32_t h0 = h2u(__floats2half2_rn(v[0], v[1]));
        uint32_t h1 = h2u(__floats2half2_rn(v[2], v[3]));
        uint32_t h2_ = h2u(__floats2half2_rn(v[4], v[5]));
        uint32_t h3 = h2u(__floats2half2_rn(v[6], v[7]));
        uint32_t addr = sbH + (u >> 2) * 8192 + sw_off(m, u & 3);
        asm volatile("st.shared.v4.b32 [%0], {%1,%2,%3,%4};"
                     :: "r"(addr), "r"(h0), "r"(h1), "r"(h2_), "r"(h3) : "memory");
    }
    __syncthreads();

    uint32_t offA[2][2], offB[2][2];
    {
        const int mr = lane & 15;
        const int uu = lane >> 4;
#pragma unroll
        for (int im = 0; im < 2; ++im)
#pragma unroll
            for (int kk = 0; kk < 2; ++kk)
                offA[im][kk] = sw_off(wm * 32 + im * 16 + mr, kk * 2 + uu);
#pragma unroll
        for (int j = 0; j < 2; ++j)
#pragma unroll
            for (int kk = 0; kk < 2; ++kk)
                offB[j][kk] = sw_off(wn * 32 + j * 16 + mr, kk * 2 + uu);
    }

    const int brow = tid >> 2;
    const int bu   = tid & 3;
    const uint32_t dB = sw_off(brow, bu);

    // prologue: 3 chunks (global chunk gc = nt*4 + kc)
#pragma unroll
    for (int s = 0; s < 3; ++s) {
        const __half* p = d_hWh + (size_t)((s >> 2) * 128 + brow) * 128 +
                          (s & 3) * 32 + bu * 8;
        cp16(sbB + s * 8192 + dB, p);
        CP_COMMIT();
    }

    float acc[2][4][4];
#pragma unroll
    for (int i = 0; i < 2; ++i)
#pragma unroll
        for (int j = 0; j < 4; ++j)
#pragma unroll
            for (int c = 0; c < 4; ++c) acc[i][j][c] = 0.f;

#pragma unroll 1
    for (int gc = 0; gc < 12; ++gc) {
        CP_WAIT2();
        __syncthreads();
        if (gc + 3 < 12) {
            const int n = gc + 3;
            const __half* p = d_hWh + (size_t)((n >> 2) * 128 + brow) * 128 +
                              (n & 3) * 32 + bu * 8;
            cp16(sbB + (n & 3) * 8192 + dB, p);
        }
        CP_COMMIT();

        const uint32_t xc  = sbH + (gc & 3) * 8192;
        const uint32_t stg = sbB + (gc & 3) * 8192;
#pragma unroll
        for (int kk = 0; kk < 2; ++kk) {
            uint32_t a[2][4], b[2][4];
#pragma unroll
            for (int im = 0; im < 2; ++im)
                ldsm4(a[im][0], a[im][1], a[im][2], a[im][3], xc + offA[im][kk]);
#pragma unroll
            for (int j = 0; j < 2; ++j)
                ldsm4(b[j][0], b[j][1], b[j][2], b[j][3], stg + offB[j][kk]);
#pragma unroll
            for (int im = 0; im < 2; ++im) {
                mma_f16(acc[im][0], a[im][0], a[im][1], a[im][2], a[im][3],
                        b[0][0], b[0][2]);
                mma_f16(acc[im][1], a[im][0], a[im][1], a[im][2], a[im][3],
                        b[0][1], b[0][3]);
                mma_f16(acc[im][2], a[im][0], a[im][1], a[im][2], a[im][3],
                        b[1][0], b[1][2]);
                mma_f16(acc[im][3], a[im][0], a[im][1], a[im][2], a[im][3],
                        b[1][1], b[1][3]);
            }
        }

        if ((gc & 3) == 3 && gc < 11) {
            // park r-gate (nt=0) / z-gate (nt=1) sums in smem, reset acc
            float* Gp = (gc >> 2) ? Gs1 : Gs0;
#pragma unroll
            for (int im = 0; im < 2; ++im) {
#pragma unroll
                for (int in_ = 0; in_ < 4; ++in_) {
                    const int row = wm * 32 + im * 16 + g;
                    const int col = wn * 32 + in_ * 8 + tg * 2;
                    *(float2*)(Gp + row * GSS + col) =
                        make_float2(acc[im][in_][0], acc[im][in_][1]);
                    *(float2*)(Gp + (row + 8) * GSS + col) =
                        make_float2(acc[im][in_][2], acc[im][in_][3]);
                    acc[im][in_][0] = acc[im][in_][1] = 0.f;
                    acc[im][in_][2] = acc[im][in_][3] = 0.f;
                }
            }
        }
    }

    // ---- fused combine epilogue (acc = ghn tile, pre-bias)
#pragma unroll
    for (int in_ = 0; in_ < 4; ++in_) {
        const int j = wn * 32 + in_ * 8 + tg * 2;
        const float2 bir = __ldg((const float2*)(bi + j));
        const float2 biz = __ldg((const float2*)(bi + 128 + j));
        const float2 bin = __ldg((const float2*)(bi + 256 + j));
        const float2 bhr = __ldg((const float2*)(bh + j));
        const float2 bhz = __ldg((const float2*)(bh + 128 + j));
        const float2 bhn = __ldg((const float2*)(bh + 256 + j));
#pragma unroll
        for (int im = 0; im < 2; ++im) {
#pragma unroll
            for (int half = 0; half < 2; ++half) {
                const int lrow = wm * 32 + im * 16 + g + half * 8;
                const int gr = m0 + lrow;
                if (gr >= NROWS) continue;
                const float* g1 = d_G1 + (size_t)gr * G3;
                float2 g1r = *(const float2*)(g1 + j);
                float2 g1z = *(const float2*)(g1 + 128 + j);
                float2 g1n = *(const float2*)(g1 + 256 + j);
                const float* hp = (gr < NU) ? si + (size_t)gr * 128
                                            : sj + (size_t)(gr - NU) * 128;
                float2 hv = *(const float2*)(hp + j);
                float ghr0 = Gs0[lrow * GSS + j],     ghr1 = Gs0[lrow * GSS + j + 1];
                float ghz0 = Gs1[lrow * GSS + j],     ghz1 = Gs1[lrow * GSS + j + 1];
                float ghn0 = acc[im][in_][half * 2],  ghn1 = acc[im][in_][half * 2 + 1];

                float r0 = sigf(g1r.x + bir.x + ghr0 + bhr.x);
                float r1 = sigf(g1r.y + bir.y + ghr1 + bhr.y);
                float z0 = sigf(g1z.x + biz.x + ghz0 + bhz.x);
                float z1 = sigf(g1z.y + biz.y + ghz1 + bhz.y);
                float n0 = tanhf(g1n.x + bin.x + r0 * (ghn0 + bhn.x));
                float n1 = tanhf(g1n.y + bin.y + r1 * (ghn1 + bhn.y));
                float2 o;
                o.x = (1.f - z0) * n0 + z0 * hv.x;
                o.y = (1.f - z1) * n1 + z1 * hv.y;
                *(float2*)(out + (size_t)gr * 128 + j) = o;
            }
        }
    }
}

// ---------------------------------------------------------------------------
extern "C" void kernel_launch(void* const* d_in, const int* in_sizes, int n_in,
                              void* d_out, int out_size) {
    const float* si   = (const float*)d_in[0];
    const float* sj   = (const float*)d_in[1];
    const float* t    = (const float*)d_in[2];
    const float* ef   = (const float*)d_in[3];
    const int*   src  = (const int*)d_in[4];
    const int*   dst  = (const int*)d_in[5];
    const float* Wi   = (const float*)d_in[6];
    const float* Wh   = (const float*)d_in[7];
    const float* bi   = (const float*)d_in[8];
    const float* bh   = (const float*)d_in[9];
    const float* freq = (const float*)d_in[10];
    float* out = (float*)d_out;

    k_init_last<<<(NU + 255) / 256, 256>>>();
    k_scan_edges<<<(NE + 255) / 256, 256>>>(src, dst);
    k_cvt_w<<<(G3 * MDIM + 255) / 256, 256>>>(Wi, Wh);

    cudaFuncSetAttribute(k_gemm1f, cudaFuncAttributeMaxDynamicSharedMemorySize, K1_SMEM);
    k_gemm1f<<<NTILES, 512, K1_SMEM>>>(si, sj, t, ef, src, dst, freq);

    cudaFuncSetAttribute(k_gemm2f, cudaFuncAttributeMaxDynamicSharedMemorySize, K2_SMEM);
    k_gemm2f<<<NTILES, 512, K2_SMEM>>>(si, sj, bi, bh, out);
}